// round 12
// baseline (speedup 1.0000x reference)
#include <cuda_runtime.h>
#include <cuda_fp16.h>
#include <cstdint>

#define D_IN     256
#define H_DIM    128
#define N_SHARE  4
#define N_EXPERTS 12
#define M_TILE   128
#define THREADS  256
#define NCHUNKS  48                      // 12 experts x 4 k64-chunks
#define CHUNK_BYTES 16384                // k64 x 128n halves

// fragment-ordered fp16 weight image: [12][16ks][8ng][32lane][16B]
__device__ __align__(16) __half g_Wh[N_EXPERTS * 32768];

// ---- shared memory layout (bytes) ----
#define OFF_A    0                       // 65536: [16ks][8mb][32lane][16B]
#define OFF_B    65536                   // 2 x 16384
#define OFF_WG   (OFF_B + 16384)         // W_gate fp32 alias of buffer 1 (16KB)
#define OFF_GS   98304                   // gates [128][17] f32 = 8704
#define OFF_BS   107008                  // biases [12][128] f32 = 6144
#define SMEM_BYTES 113152

static __device__ __forceinline__ void mma_f16(float* d, const uint32_t* a,
                                               uint32_t b0, uint32_t b1) {
    asm volatile(
        "mma.sync.aligned.m16n8k16.row.col.f32.f16.f16.f32 "
        "{%0,%1,%2,%3}, {%4,%5,%6,%7}, {%8,%9}, {%0,%1,%2,%3};\n"
        : "+f"(d[0]), "+f"(d[1]), "+f"(d[2]), "+f"(d[3])
        : "r"(a[0]), "r"(a[1]), "r"(a[2]), "r"(a[3]), "r"(b0), "r"(b1));
}
static __device__ __forceinline__ uint32_t h2u(float lo, float hi) {
    half2 h = __floats2half2_rn(lo, hi);
    return *(uint32_t*)&h;
}

// ---------------- output zero-init ----------------
__global__ void dmoe_zero(float4* out) {
    out[blockIdx.x * 1024 + threadIdx.x] = make_float4(0.f, 0.f, 0.f, 0.f);
}

// ---------------- weight prep: fp16 fragment-ordered image ----------------
__global__ void dmoe_wprep(const float* __restrict__ Wsh,
                           const float* __restrict__ Wtk) {
    int idx = blockIdx.x * 256 + threadIdx.x;     // slot index
    if (idx >= N_EXPERTS * 4096) return;
    int e = idx >> 12;
    int s = idx & 4095;
    int lane = s & 31, ng = (s >> 5) & 7, ks = s >> 8;
    int gid = lane >> 2, tig = lane & 3;
    int k0 = ks * 16 + tig * 2;
    int na = ng * 16 + gid, nb = na + 8;
    const float* W = (e < N_SHARE)
        ? (Wsh + (size_t)e * (D_IN * H_DIM))
        : (Wtk + (size_t)(e - N_SHARE) * (D_IN * H_DIM));
    uint4 v;
    v.x = h2u(W[(size_t)k0 * H_DIM + na],       W[(size_t)(k0+1) * H_DIM + na]);
    v.y = h2u(W[(size_t)(k0+8) * H_DIM + na],   W[(size_t)(k0+9) * H_DIM + na]);
    v.z = h2u(W[(size_t)k0 * H_DIM + nb],       W[(size_t)(k0+1) * H_DIM + nb]);
    v.w = h2u(W[(size_t)(k0+8) * H_DIM + nb],   W[(size_t)(k0+9) * H_DIM + nb]);
    *(uint4*)((char*)g_Wh + (size_t)e * 65536 + (size_t)s * 16) = v;
}

// ---------------- main fused kernel ----------------
__global__ __launch_bounds__(THREADS, 2)
void dmoe_fused_kernel(const float* __restrict__ x,
                       const float* __restrict__ bsh,
                       const float* __restrict__ btk,
                       const float* __restrict__ Wg,
                       const float* __restrict__ bg,
                       float* __restrict__ out,
                       int Btot)
{
    extern __shared__ char smem[];
    float* wgs = (float*)(smem + OFF_WG);
    float* gs  = (float*)(smem + OFF_GS);
    float* bs  = (float*)(smem + OFF_BS);

    const int tid  = threadIdx.x;
    const int warp = tid >> 5;
    const int lane = tid & 31;
    const int gid  = lane >> 2;
    const int tig  = lane & 3;
    const int m0   = (warp >> 1) * 32;       // 0,32,64,96
    const int mbA  = (warp >> 1) * 2;        // A m-block base (16-row blocks)
    const int hb   = warp & 1;               // 64-col h block
    const int h0   = hb * 64;
    const int row0 = blockIdx.x * M_TILE;

    auto issue_chunk = [&](int n) {          // chunk n -> buffer n&1
        const char* src = (const char*)g_Wh
                        + (size_t)(n >> 2) * 65536 + (n & 3) * CHUNK_BYTES + tid * 16;
        unsigned dst = (unsigned)__cvta_generic_to_shared(smem + OFF_B)
                     + (n & 1) * CHUNK_BYTES + tid * 16;
        #pragma unroll
        for (int j = 0; j < 4; ++j)
            asm volatile("cp.async.cg.shared.global [%0], [%1], 16;\n"
                         :: "r"(dst + j * 4096), "l"(src + j * 4096));
        asm volatile("cp.async.commit_group;\n" ::: "memory");
    };

    issue_chunk(0);    // prologue -> buffer 0 only (buffer 1 holds W_gate)

    // --- stage x tile (128 x 256) into fp16 A-fragment order
    {
        #pragma unroll
        for (int j = 0; j < 16; ++j) {
            int s = j * THREADS + tid;       // 4096 slots
            int ln = s & 31, mb = (s >> 5) & 7, ks = s >> 8;
            int g = ln >> 2, tg = ln & 3;
            int r = row0 + mb * 16 + g;
            int k0 = ks * 16 + tg * 2;
            const float* xp = x + (size_t)r * D_IN;
            float2 v00 = *(const float2*)(xp + k0);
            float2 v10 = *(const float2*)(xp + 8 * D_IN + k0);
            float2 v01 = *(const float2*)(xp + k0 + 8);
            float2 v11 = *(const float2*)(xp + 8 * D_IN + k0 + 8);
            uint4 a;
            a.x = h2u(v00.x, v00.y);
            a.y = h2u(v10.x, v10.y);
            a.z = h2u(v01.x, v01.y);
            a.w = h2u(v11.x, v11.y);
            *(uint4*)(smem + OFF_A + (size_t)s * 16) = a;
        }
    }
    // --- stage W_gate [2][256][8] fp32 into buffer-1 alias (linear copy)
    {
        const float4* wgg = (const float4*)Wg;
        #pragma unroll
        for (int j = 0; j < 4; ++j) {
            int idx = j * THREADS + tid;     // 1024 float4
            *(float4*)(wgs + idx * 4) = wgg[idx];
        }
    }
    // --- biases
    for (int i = tid; i < N_EXPERTS * H_DIM; i += THREADS) {
        int e = i >> 7, h = i & 127;
        bs[i] = (e < N_SHARE) ? bsh[e * H_DIM + h]
                              : btk[(e - N_SHARE) * H_DIM + h];
    }
    __syncthreads();

    // --- gates (x from global, W_gate from smem) + softmax, 128 rows
    {
        int half_ = lane >> 4;
        int gi = lane & 15, t = gi >> 3, gg = gi & 7;
        const float* wcol = wgs + t * 2048 + gg;
        float bias = bg[t * 8 + gg];
        #pragma unroll
        for (int i = 0; i < 8; ++i) {
            int row = 2 * (warp + 8 * i) + half_;
            const float* xr = x + (size_t)(row0 + row) * D_IN;
            float acc = 0.f;
            #pragma unroll 8
            for (int k = 0; k < D_IN; ++k)
                acc = fmaf(xr[k], wcol[k * 8], acc);
            acc += bias;
            float mx = acc;
            mx = fmaxf(mx, __shfl_xor_sync(0xffffffffu, mx, 1));
            mx = fmaxf(mx, __shfl_xor_sync(0xffffffffu, mx, 2));
            mx = fmaxf(mx, __shfl_xor_sync(0xffffffffu, mx, 4));
            float ev = __expf(acc - mx);
            float s = ev;
            s += __shfl_xor_sync(0xffffffffu, s, 1);
            s += __shfl_xor_sync(0xffffffffu, s, 2);
            s += __shfl_xor_sync(0xffffffffu, s, 4);
            gs[row * 17 + gi] = ev / s;
        }
    }
    __syncthreads();

    // --- main loop: 48 chunks, double-buffered; acc 32m x 64n per warp
    #pragma unroll 1
    for (int e = 0; e < N_EXPERTS; ++e) {
        float acc[2][8][4];
        #pragma unroll
        for (int mt = 0; mt < 2; ++mt)
            #pragma unroll
            for (int j = 0; j < 8; ++j)
                #pragma unroll
                for (int c = 0; c < 4; ++c)
                    acc[mt][j][c] = 0.f;

        #pragma unroll 1
        for (int kc = 0; kc < 4; ++kc) {
            int ch = e * 4 + kc;
            if (ch + 1 < NCHUNKS) {
                issue_chunk(ch + 1);
                asm volatile("cp.async.wait_group 1;\n" ::: "memory");
            } else {
                asm volatile("cp.async.wait_group 0;\n" ::: "memory");
            }
            __syncthreads();

            const char* bufp = smem + OFF_B + (ch & 1) * CHUNK_BYTES
                             + hb * 2048 + lane * 16;
            const char* ap   = smem + OFF_A + kc * 16384
                             + mbA * 512 + lane * 16;
            #pragma unroll
            for (int ksl = 0; ksl < 4; ++ksl) {
                uint4 A0 = *(const uint4*)(ap + ksl * 4096);
                uint4 A1 = *(const uint4*)(ap + ksl * 4096 + 512);
                uint4 B0 = *(const uint4*)(bufp + ksl * 4096);
                uint4 B1 = *(const uint4*)(bufp + ksl * 4096 + 512);
                uint4 B2 = *(const uint4*)(bufp + ksl * 4096 + 1024);
                uint4 B3 = *(const uint4*)(bufp + ksl * 4096 + 1536);
                const uint32_t* ua0 = (const uint32_t*)&A0;
                const uint32_t* ua1 = (const uint32_t*)&A1;
                mma_f16(acc[0][0], ua0, B0.x, B0.y);
                mma_f16(acc[0][1], ua0, B0.z, B0.w);
                mma_f16(acc[0][2], ua0, B1.x, B1.y);
                mma_f16(acc[0][3], ua0, B1.z, B1.w);
                mma_f16(acc[0][4], ua0, B2.x, B2.y);
                mma_f16(acc[0][5], ua0, B2.z, B2.w);
                mma_f16(acc[0][6], ua0, B3.x, B3.y);
                mma_f16(acc[0][7], ua0, B3.z, B3.w);
                mma_f16(acc[1][0], ua1, B0.x, B0.y);
                mma_f16(acc[1][1], ua1, B0.z, B0.w);
                mma_f16(acc[1][2], ua1, B1.x, B1.y);
                mma_f16(acc[1][3], ua1, B1.z, B1.w);
                mma_f16(acc[1][4], ua1, B2.x, B2.y);
                mma_f16(acc[1][5], ua1, B2.z, B2.w);
                mma_f16(acc[1][6], ua1, B3.x, B3.y);
                mma_f16(acc[1][7], ua1, B3.z, B3.w);
            }
            __syncthreads();
        }

        // --- epilogue: bias + ReLU + gate-scaled atomic accumulate
        #pragma unroll
        for (int mt = 0; mt < 2; ++mt) {
            int rA = m0 + mt * 16 + gid;
            int rB = rA + 8;
            float* oA0 = out + ((size_t)row0 + rA) * H_DIM;
            float* oB0 = out + ((size_t)row0 + rB) * H_DIM;
            float* oA1 = oA0 + (size_t)Btot * H_DIM;
            float* oB1 = oB0 + (size_t)Btot * H_DIM;
            if (e < N_SHARE) {
                float gA0 = gs[rA * 17 + e],     gB0 = gs[rB * 17 + e];
                float gA1 = gs[rA * 17 + 8 + e], gB1 = gs[rB * 17 + 8 + e];
                #pragma unroll
                for (int j = 0; j < 8; ++j) {
                    int h = h0 + (j >> 1) * 16 + (j & 1) * 8 + tig * 2;
                    float b0 = bs[e * H_DIM + h];
                    float b1 = bs[e * H_DIM + h + 1];
                    float v0 = fmaxf(acc[mt][j][0] + b0, 0.f);
                    float v1 = fmaxf(acc[mt][j][1] + b1, 0.f);
                    float v2 = fmaxf(acc[mt][j][2] + b0, 0.f);
                    float v3 = fmaxf(acc[mt][j][3] + b1, 0.f);
                    atomicAdd(oA0 + h,     gA0 * v0);
                    atomicAdd(oA0 + h + 1, gA0 * v1);
                    atomicAdd(oB0 + h,     gB0 * v2);
                    atomicAdd(oB0 + h + 1, gB0 * v3);
                    atomicAdd(oA1 + h,     gA1 * v0);
                    atomicAdd(oA1 + h + 1, gA1 * v1);
                    atomicAdd(oB1 + h,     gB1 * v2);
                    atomicAdd(oB1 + h + 1, gB1 * v3);
                }
            } else {
                int et = e - N_SHARE;
                int tt = et >> 2;
                int gcol = tt * 8 + 4 + (et & 3);
                float gA = gs[rA * 17 + gcol];
                float gB = gs[rB * 17 + gcol];
                float* oA = tt ? oA1 : oA0;
                float* oB = tt ? oB1 : oB0;
                #pragma unroll
                for (int j = 0; j < 8; ++j) {
                    int h = h0 + (j >> 1) * 16 + (j & 1) * 8 + tig * 2;
                    float b0 = bs[e * H_DIM + h];
                    float b1 = bs[e * H_DIM + h + 1];
                    atomicAdd(oA + h,     gA * fmaxf(acc[mt][j][0] + b0, 0.f));
                    atomicAdd(oA + h + 1, gA * fmaxf(acc[mt][j][1] + b1, 0.f));
                    atomicAdd(oB + h,     gB * fmaxf(acc[mt][j][2] + b0, 0.f));
                    atomicAdd(oB + h + 1, gB * fmaxf(acc[mt][j][3] + b1, 0.f));
                }
            }
        }
    }
}

extern "C" void kernel_launch(void* const* d_in, const int* in_sizes, int n_in,
                              void* d_out, int out_size) {
    const float* x   = (const float*)d_in[0];
    const float* Wsh = (const float*)d_in[1];
    const float* bsh = (const float*)d_in[2];
    const float* Wtk = (const float*)d_in[3];
    const float* btk = (const float*)d_in[4];
    const float* Wg  = (const float*)d_in[5];
    const float* bg  = (const float*)d_in[6];
    float* out = (float*)d_out;

    int Btot = in_sizes[0] / D_IN;           // 32768
    // zero output (out_size = 2*B*H floats, divisible by 4096)
    dmoe_zero<<<out_size / 4096, 1024>>>((float4*)out);
    int nslots = N_EXPERTS * 4096;           // 49152
    dmoe_wprep<<<(nslots + 255) / 256, 256>>>(Wsh, Wtk);

    cudaFuncSetAttribute(dmoe_fused_kernel,
                         cudaFuncAttributeMaxDynamicSharedMemorySize, SMEM_BYTES);
    dmoe_fused_kernel<<<Btot / M_TILE, THREADS, SMEM_BYTES>>>(
        x, bsh, btk, Wg, bg, out, Btot);
}

// round 13
// speedup vs baseline: 1.1867x; 1.1867x over previous
#include <cuda_runtime.h>
#include <cuda_fp16.h>
#include <cstdint>

#define D_IN     256
#define H_DIM    128
#define N_SHARE  4
#define N_EXPERTS 12
#define M_TILE   64
#define THREADS  256

// fragment-ordered fp16 weight image: [12][16ks][8ng][32lane][16B]
// byte(e,ks,ng,lane) = e*65536 + ks*4096 + ng*512 + lane*16
__device__ __align__(16) __half g_Wh[N_EXPERTS * 32768];

// ---- shared memory layout (bytes) ----
#define OFF_A    0          // 32768: [16ks][4mb][32lane][16B]
#define OFF_WG   32768      // W_gate fp32 [2][256][8] = 16384
#define OFF_GS   49152      // gates [64][17] f32 = 4352
#define OFF_BS   53504      // biases [12][128] f32 = 6144
#define SMEM_BYTES 59648

static __device__ __forceinline__ void mma_f16(float* d, const uint32_t* a,
                                               uint32_t b0, uint32_t b1) {
    asm volatile(
        "mma.sync.aligned.m16n8k16.row.col.f32.f16.f16.f32 "
        "{%0,%1,%2,%3}, {%4,%5,%6,%7}, {%8,%9}, {%0,%1,%2,%3};\n"
        : "+f"(d[0]), "+f"(d[1]), "+f"(d[2]), "+f"(d[3])
        : "r"(a[0]), "r"(a[1]), "r"(a[2]), "r"(a[3]), "r"(b0), "r"(b1));
}
static __device__ __forceinline__ uint32_t h2u(float lo, float hi) {
    half2 h = __floats2half2_rn(lo, hi);
    return *(uint32_t*)&h;
}

// ---------------- weight prep: fp16 fragment-ordered image ----------------
__global__ void dmoe_wprep(const float* __restrict__ Wsh,
                           const float* __restrict__ Wtk) {
    int idx = blockIdx.x * 256 + threadIdx.x;     // slot index
    if (idx >= N_EXPERTS * 4096) return;
    int e = idx >> 12;
    int s = idx & 4095;
    int lane = s & 31, ng = (s >> 5) & 7, ks = s >> 8;
    int gid = lane >> 2, tig = lane & 3;
    int k0 = ks * 16 + tig * 2;
    int na = ng * 16 + gid, nb = na + 8;
    const float* W = (e < N_SHARE)
        ? (Wsh + (size_t)e * (D_IN * H_DIM))
        : (Wtk + (size_t)(e - N_SHARE) * (D_IN * H_DIM));
    uint4 v;
    v.x = h2u(W[(size_t)k0 * H_DIM + na],       W[(size_t)(k0+1) * H_DIM + na]);
    v.y = h2u(W[(size_t)(k0+8) * H_DIM + na],   W[(size_t)(k0+9) * H_DIM + na]);
    v.z = h2u(W[(size_t)k0 * H_DIM + nb],       W[(size_t)(k0+1) * H_DIM + nb]);
    v.w = h2u(W[(size_t)(k0+8) * H_DIM + nb],   W[(size_t)(k0+9) * H_DIM + nb]);
    *(uint4*)((char*)g_Wh + (size_t)e * 65536 + (size_t)s * 16) = v;
}

// ---------------- main fused kernel ----------------
__global__ __launch_bounds__(THREADS, 2)
void dmoe_fused_kernel(const float* __restrict__ x,
                       const float* __restrict__ bsh,
                       const float* __restrict__ btk,
                       const float* __restrict__ Wg,
                       const float* __restrict__ bg,
                       float* __restrict__ out,
                       int Btot)
{
    extern __shared__ char smem[];
    float* wgs = (float*)(smem + OFF_WG);
    float* gs  = (float*)(smem + OFF_GS);
    float* bs  = (float*)(smem + OFF_BS);

    const int tid  = threadIdx.x;
    const int warp = tid >> 5;
    const int lane = tid & 31;
    const int gid  = lane >> 2;
    const int tig  = lane & 3;
    const int m0   = (warp >> 2) * 32;       // 0 or 32
    const int mbA  = (warp >> 2) * 2;        // A m-block base (16-row blocks)
    const int hb   = warp & 3;               // 32-col h block
    const int row0 = blockIdx.x * M_TILE;

    // --- stage x tile (64 x 256) into fp16 A-fragment order
    {
        #pragma unroll
        for (int j = 0; j < 8; ++j) {
            int s = j * THREADS + tid;       // 2048 slots
            int ln = s & 31, mb = (s >> 5) & 3, ks = s >> 7;
            int g = ln >> 2, tg = ln & 3;
            int r = row0 + mb * 16 + g;
            int k0 = ks * 16 + tg * 2;
            const float* xp = x + (size_t)r * D_IN;
            float2 v00 = *(const float2*)(xp + k0);
            float2 v10 = *(const float2*)(xp + 8 * D_IN + k0);
            float2 v01 = *(const float2*)(xp + k0 + 8);
            float2 v11 = *(const float2*)(xp + 8 * D_IN + k0 + 8);
            uint4 a;
            a.x = h2u(v00.x, v00.y);
            a.y = h2u(v10.x, v10.y);
            a.z = h2u(v01.x, v01.y);
            a.w = h2u(v11.x, v11.y);
            *(uint4*)(smem + OFF_A + (size_t)s * 16) = a;
        }
    }
    // --- stage W_gate [2][256][8] fp32 (linear copy)
    {
        const float4* wgg = (const float4*)Wg;
        #pragma unroll
        for (int j = 0; j < 4; ++j) {
            int idx = j * THREADS + tid;     // 1024 float4
            *(float4*)(wgs + idx * 4) = wgg[idx];
        }
    }
    // --- biases
    for (int i = tid; i < N_EXPERTS * H_DIM; i += THREADS) {
        int e = i >> 7, h = i & 127;
        bs[i] = (e < N_SHARE) ? bsh[e * H_DIM + h]
                              : btk[(e - N_SHARE) * H_DIM + h];
    }
    __syncthreads();

    // --- gates (x from global, W_gate from smem) + softmax
    {
        int half_ = lane >> 4;
        int gi = lane & 15, t = gi >> 3, gg = gi & 7;
        const float* wcol = wgs + t * 2048 + gg;
        float bias = bg[t * 8 + gg];
        #pragma unroll
        for (int i = 0; i < 4; ++i) {
            int row = 2 * (warp + 8 * i) + half_;
            const float* xr = x + (size_t)(row0 + row) * D_IN;
            float acc = 0.f;
            #pragma unroll 8
            for (int k = 0; k < D_IN; ++k)
                acc = fmaf(xr[k], wcol[k * 8], acc);
            acc += bias;
            float mx = acc;
            mx = fmaxf(mx, __shfl_xor_sync(0xffffffffu, mx, 1));
            mx = fmaxf(mx, __shfl_xor_sync(0xffffffffu, mx, 2));
            mx = fmaxf(mx, __shfl_xor_sync(0xffffffffu, mx, 4));
            float ev = __expf(acc - mx);
            float s = ev;
            s += __shfl_xor_sync(0xffffffffu, s, 1);
            s += __shfl_xor_sync(0xffffffffu, s, 2);
            s += __shfl_xor_sync(0xffffffffu, s, 4);
            gs[row * 17 + gi] = ev / s;
        }
    }
    __syncthreads();
    // ======= no further barriers: pure dataflow from here on =======

    float tw[2][2][4][4];
    #pragma unroll
    for (int t = 0; t < 2; ++t)
        #pragma unroll
        for (int mt = 0; mt < 2; ++mt)
            #pragma unroll
            for (int nt = 0; nt < 4; ++nt)
                #pragma unroll
                for (int c = 0; c < 4; ++c)
                    tw[t][mt][nt][c] = 0.f;

    const char* ap    = smem + OFF_A + mbA * 512 + lane * 16;
    const char* bbase = (const char*)g_Wh + (size_t)(2 * hb) * 512 + (size_t)lane * 16;

    // --- main loop: 12 experts, B streamed straight from L2 via LDG.128.NC
    #pragma unroll 1
    for (int e = 0; e < N_EXPERTS; ++e) {
        float acc[2][4][4];
        #pragma unroll
        for (int mt = 0; mt < 2; ++mt)
            #pragma unroll
            for (int nt = 0; nt < 4; ++nt)
                #pragma unroll
                for (int c = 0; c < 4; ++c)
                    acc[mt][nt][c] = 0.f;

        const char* bp = bbase + (size_t)e * 65536;
        #pragma unroll 4
        for (int ks = 0; ks < 16; ++ks) {
            uint4 A0 = *(const uint4*)(ap + ks * 2048);
            uint4 A1 = *(const uint4*)(ap + ks * 2048 + 512);
            uint4 B0 = __ldg((const uint4*)(bp + ks * 4096));
            uint4 B1 = __ldg((const uint4*)(bp + ks * 4096 + 512));
            const uint32_t* ua0 = (const uint32_t*)&A0;
            const uint32_t* ua1 = (const uint32_t*)&A1;
            mma_f16(acc[0][0], ua0, B0.x, B0.y);
            mma_f16(acc[0][1], ua0, B0.z, B0.w);
            mma_f16(acc[0][2], ua0, B1.x, B1.y);
            mma_f16(acc[0][3], ua0, B1.z, B1.w);
            mma_f16(acc[1][0], ua1, B0.x, B0.y);
            mma_f16(acc[1][1], ua1, B0.z, B0.w);
            mma_f16(acc[1][2], ua1, B1.x, B1.y);
            mma_f16(acc[1][3], ua1, B1.z, B1.w);
        }

        // --- epilogue: bias + ReLU + gate-weighted accumulate (registers)
        #pragma unroll
        for (int mt = 0; mt < 2; ++mt) {
            int rA = m0 + mt * 16 + gid;
            int rB = rA + 8;
            if (e < N_SHARE) {
                float gA0 = gs[rA * 17 + e],     gB0 = gs[rB * 17 + e];
                float gA1 = gs[rA * 17 + 8 + e], gB1 = gs[rB * 17 + 8 + e];
                #pragma unroll
                for (int nt = 0; nt < 4; ++nt) {
                    int h = hb * 32 + nt * 8 + tig * 2;
                    float b0 = bs[e * H_DIM + h];
                    float b1 = bs[e * H_DIM + h + 1];
                    float v0 = fmaxf(acc[mt][nt][0] + b0, 0.f);
                    float v1 = fmaxf(acc[mt][nt][1] + b1, 0.f);
                    float v2 = fmaxf(acc[mt][nt][2] + b0, 0.f);
                    float v3 = fmaxf(acc[mt][nt][3] + b1, 0.f);
                    tw[0][mt][nt][0] += gA0 * v0;  tw[0][mt][nt][1] += gA0 * v1;
                    tw[0][mt][nt][2] += gB0 * v2;  tw[0][mt][nt][3] += gB0 * v3;
                    tw[1][mt][nt][0] += gA1 * v0;  tw[1][mt][nt][1] += gA1 * v1;
                    tw[1][mt][nt][2] += gB1 * v2;  tw[1][mt][nt][3] += gB1 * v3;
                }
            } else {
                int et = e - N_SHARE;
                int tt = et >> 2;
                int gcol = tt * 8 + 4 + (et & 3);
                float gA = gs[rA * 17 + gcol];
                float gB = gs[rB * 17 + gcol];
                float* twt = &tw[tt][mt][0][0];
                #pragma unroll
                for (int nt = 0; nt < 4; ++nt) {
                    int h = hb * 32 + nt * 8 + tig * 2;
                    float b0 = bs[e * H_DIM + h];
                    float b1 = bs[e * H_DIM + h + 1];
                    twt[nt * 4 + 0] += gA * fmaxf(acc[mt][nt][0] + b0, 0.f);
                    twt[nt * 4 + 1] += gA * fmaxf(acc[mt][nt][1] + b1, 0.f);
                    twt[nt * 4 + 2] += gB * fmaxf(acc[mt][nt][2] + b0, 0.f);
                    twt[nt * 4 + 3] += gB * fmaxf(acc[mt][nt][3] + b1, 0.f);
                }
            }
        }
    }

    // --- write towers [2][B][128]
    #pragma unroll
    for (int t = 0; t < 2; ++t) {
        #pragma unroll
        for (int mt = 0; mt < 2; ++mt) {
            size_t rA = (size_t)row0 + m0 + mt * 16 + gid;
            float* baseA = out + ((size_t)t * Btot + rA) * H_DIM;
            float* baseB = baseA + 8 * H_DIM;
            #pragma unroll
            for (int nt = 0; nt < 4; ++nt) {
                int h = hb * 32 + nt * 8 + tig * 2;
                *(float2*)(baseA + h) = make_float2(tw[t][mt][nt][0], tw[t][mt][nt][1]);
                *(float2*)(baseB + h) = make_float2(tw[t][mt][nt][2], tw[t][mt][nt][3]);
            }
        }
    }
}

extern "C" void kernel_launch(void* const* d_in, const int* in_sizes, int n_in,
                              void* d_out, int out_size) {
    const float* x   = (const float*)d_in[0];
    const float* Wsh = (const float*)d_in[1];
    const float* bsh = (const float*)d_in[2];
    const float* Wtk = (const float*)d_in[3];
    const float* btk = (const float*)d_in[4];
    const float* Wg  = (const float*)d_in[5];
    const float* bg  = (const float*)d_in[6];
    float* out = (float*)d_out;

    int Btot = in_sizes[0] / D_IN;           // 32768
    int nslots = N_EXPERTS * 4096;           // 49152
    dmoe_wprep<<<(nslots + 255) / 256, 256>>>(Wsh, Wtk);

    cudaFuncSetAttribute(dmoe_fused_kernel,
                         cudaFuncAttributeMaxDynamicSharedMemorySize, SMEM_BYTES);
    dmoe_fused_kernel<<<Btot / M_TILE, THREADS, SMEM_BYTES>>>(
        x, bsh, btk, Wg, bg, out, Btot);
}

// round 14
// speedup vs baseline: 1.7508x; 1.4754x over previous
#include <cuda_runtime.h>
#include <cuda_fp16.h>
#include <cstdint>

#define D_IN     256
#define H_DIM    128
#define N_SHARE  4
#define N_EXPERTS 12
#define M_TILE   64
#define THREADS  256

// fragment-ordered fp16 weight image: [12][16ks][8ng][32lane][16B]
__device__ __align__(16) __half g_Wh[N_EXPERTS * 32768];
// fragment-ordered fp16 gate-weight image: [16ks][32lane][16B] (N=16)
__device__ __align__(16) __half g_Wgh[4096];

// ---- shared memory layout (bytes) ----
#define OFF_A    0          // 32768: [16ks][4mb][32lane][16B]
#define OFF_GS   32768      // gates [64][17] f32 = 4352
#define OFF_BS   37120      // biases [12][128] f32 = 6144
#define SMEM_BYTES 43264

static __device__ __forceinline__ void mma_f16(float* d, const uint32_t* a,
                                               uint32_t b0, uint32_t b1) {
    asm volatile(
        "mma.sync.aligned.m16n8k16.row.col.f32.f16.f16.f32 "
        "{%0,%1,%2,%3}, {%4,%5,%6,%7}, {%8,%9}, {%0,%1,%2,%3};\n"
        : "+f"(d[0]), "+f"(d[1]), "+f"(d[2]), "+f"(d[3])
        : "r"(a[0]), "r"(a[1]), "r"(a[2]), "r"(a[3]), "r"(b0), "r"(b1));
}
static __device__ __forceinline__ uint32_t h2u(float lo, float hi) {
    half2 h = __floats2half2_rn(lo, hi);
    return *(uint32_t*)&h;
}

// ---------------- weight prep: fp16 fragment-ordered images ----------------
__global__ void dmoe_wprep(const float* __restrict__ Wsh,
                           const float* __restrict__ Wtk,
                           const float* __restrict__ Wg) {
    int idx = blockIdx.x * 256 + threadIdx.x;     // slot index
    if (idx < N_EXPERTS * 4096) {
        int e = idx >> 12;
        int s = idx & 4095;
        int lane = s & 31, ng = (s >> 5) & 7, ks = s >> 8;
        int gid = lane >> 2, tig = lane & 3;
        int k0 = ks * 16 + tig * 2;
        int na = ng * 16 + gid, nb = na + 8;
        const float* W = (e < N_SHARE)
            ? (Wsh + (size_t)e * (D_IN * H_DIM))
            : (Wtk + (size_t)(e - N_SHARE) * (D_IN * H_DIM));
        uint4 v;
        v.x = h2u(W[(size_t)k0 * H_DIM + na],     W[(size_t)(k0+1) * H_DIM + na]);
        v.y = h2u(W[(size_t)(k0+8) * H_DIM + na], W[(size_t)(k0+9) * H_DIM + na]);
        v.z = h2u(W[(size_t)k0 * H_DIM + nb],     W[(size_t)(k0+1) * H_DIM + nb]);
        v.w = h2u(W[(size_t)(k0+8) * H_DIM + nb], W[(size_t)(k0+9) * H_DIM + nb]);
        *(uint4*)((char*)g_Wh + (size_t)e * 65536 + (size_t)s * 16) = v;
    } else if (idx < N_EXPERTS * 4096 + 512) {
        // gate image: n in [0,16): col n -> (t=n>>3, g=n&7), Wg[t][k][g]
        int s = idx - N_EXPERTS * 4096;           // 0..511
        int lane = s & 31, ks = s >> 5;           // ks 0..15
        int gid = lane >> 2, tig = lane & 3;
        int k0 = ks * 16 + tig * 2;
        int na = gid, nb = gid + 8;
        #define GV(k, n) Wg[((n) >> 3) * 2048 + (k) * 8 + ((n) & 7)]
        uint4 v;
        v.x = h2u(GV(k0, na),     GV(k0 + 1, na));
        v.y = h2u(GV(k0 + 8, na), GV(k0 + 9, na));
        v.z = h2u(GV(k0, nb),     GV(k0 + 1, nb));
        v.w = h2u(GV(k0 + 8, nb), GV(k0 + 9, nb));
        #undef GV
        *(uint4*)((char*)g_Wgh + s * 16) = v;
    }
}

// ---------------- main fused kernel ----------------
__global__ __launch_bounds__(THREADS, 2)
void dmoe_fused_kernel(const float* __restrict__ x,
                       const float* __restrict__ bsh,
                       const float* __restrict__ btk,
                       const float* __restrict__ bg,
                       float* __restrict__ out,
                       int Btot)
{
    extern __shared__ char smem[];
    float* gs = (float*)(smem + OFF_GS);
    float* bs = (float*)(smem + OFF_BS);

    const int tid  = threadIdx.x;
    const int warp = tid >> 5;
    const int lane = tid & 31;
    const int gid  = lane >> 2;
    const int tig  = lane & 3;
    const int m0   = (warp >> 2) * 32;       // 0 or 32
    const int mbA  = (warp >> 2) * 2;        // A m-block base (16-row blocks)
    const int hb   = warp & 3;               // 32-col h block
    const int row0 = blockIdx.x * M_TILE;

    // --- stage x tile (64 x 256) into fp16 A-fragment order
    {
        #pragma unroll
        for (int j = 0; j < 8; ++j) {
            int s = j * THREADS + tid;       // 2048 slots
            int ln = s & 31, mb = (s >> 5) & 3, ks = s >> 7;
            int g = ln >> 2, tg = ln & 3;
            int r = row0 + mb * 16 + g;
            int k0 = ks * 16 + tg * 2;
            const float* xp = x + (size_t)r * D_IN;
            float2 v00 = *(const float2*)(xp + k0);
            float2 v10 = *(const float2*)(xp + 8 * D_IN + k0);
            float2 v01 = *(const float2*)(xp + k0 + 8);
            float2 v11 = *(const float2*)(xp + 8 * D_IN + k0 + 8);
            uint4 a;
            a.x = h2u(v00.x, v00.y);
            a.y = h2u(v10.x, v10.y);
            a.z = h2u(v01.x, v01.y);
            a.w = h2u(v11.x, v11.y);
            *(uint4*)(smem + OFF_A + (size_t)s * 16) = a;
        }
    }
    // --- biases
    for (int i = tid; i < N_EXPERTS * H_DIM; i += THREADS) {
        int e = i >> 7, h = i & 127;
        bs[i] = (e < N_SHARE) ? bsh[e * H_DIM + h]
                              : btk[(e - N_SHARE) * H_DIM + h];
    }
    __syncthreads();

    const char* ap    = smem + OFF_A + mbA * 512 + lane * 16;
    const char* bbase = (const char*)g_Wh + (size_t)(2 * hb) * 512 + (size_t)lane * 16;

    // --- gates on the tensor core: logits[32 rows][16] from staged A
    {
        float ga[2][2][4];
        #pragma unroll
        for (int mt = 0; mt < 2; ++mt)
            #pragma unroll
            for (int g2 = 0; g2 < 2; ++g2)
                #pragma unroll
                for (int c = 0; c < 4; ++c)
                    ga[mt][g2][c] = 0.f;
        const char* gwp = (const char*)g_Wgh + lane * 16;
        #pragma unroll 4
        for (int ks = 0; ks < 16; ++ks) {
            uint4 A0 = *(const uint4*)(ap + ks * 2048);
            uint4 A1 = *(const uint4*)(ap + ks * 2048 + 512);
            uint4 G  = __ldg((const uint4*)(gwp + ks * 512));
            const uint32_t* ua0 = (const uint32_t*)&A0;
            const uint32_t* ua1 = (const uint32_t*)&A1;
            mma_f16(ga[0][0], ua0, G.x, G.y);
            mma_f16(ga[0][1], ua0, G.z, G.w);
            mma_f16(ga[1][0], ua1, G.x, G.y);
            mma_f16(ga[1][1], ua1, G.z, G.w);
        }
        // softmax in registers: thread holds cols {2tig,2tig+1} of each task
        float bg0a = bg[tig * 2],     bg0b = bg[tig * 2 + 1];
        float bg1a = bg[8 + tig * 2], bg1b = bg[9 + tig * 2];
        #pragma unroll
        for (int mt = 0; mt < 2; ++mt) {
            #pragma unroll
            for (int hf = 0; hf < 2; ++hf) {
                int row = m0 + mt * 16 + hf * 8 + gid;
                float l0a = ga[mt][0][hf * 2]     + bg0a;
                float l0b = ga[mt][0][hf * 2 + 1] + bg0b;
                float l1a = ga[mt][1][hf * 2]     + bg1a;
                float l1b = ga[mt][1][hf * 2 + 1] + bg1b;
                float mx0 = fmaxf(l0a, l0b);
                mx0 = fmaxf(mx0, __shfl_xor_sync(0xffffffffu, mx0, 1));
                mx0 = fmaxf(mx0, __shfl_xor_sync(0xffffffffu, mx0, 2));
                float e0a = __expf(l0a - mx0), e0b = __expf(l0b - mx0);
                float s0 = e0a + e0b;
                s0 += __shfl_xor_sync(0xffffffffu, s0, 1);
                s0 += __shfl_xor_sync(0xffffffffu, s0, 2);
                float inv0 = 1.f / s0;
                gs[row * 17 + tig * 2]     = e0a * inv0;
                gs[row * 17 + tig * 2 + 1] = e0b * inv0;
                float mx1 = fmaxf(l1a, l1b);
                mx1 = fmaxf(mx1, __shfl_xor_sync(0xffffffffu, mx1, 1));
                mx1 = fmaxf(mx1, __shfl_xor_sync(0xffffffffu, mx1, 2));
                float e1a = __expf(l1a - mx1), e1b = __expf(l1b - mx1);
                float s1 = e1a + e1b;
                s1 += __shfl_xor_sync(0xffffffffu, s1, 1);
                s1 += __shfl_xor_sync(0xffffffffu, s1, 2);
                float inv1 = 1.f / s1;
                gs[row * 17 + 8 + tig * 2] = e1a * inv1;
                gs[row * 17 + 9 + tig * 2] = e1b * inv1;
            }
        }
    }
    __syncthreads();
    // ======= no further barriers: pure dataflow from here on =======

    float tw[2][2][4][4];
    #pragma unroll
    for (int t = 0; t < 2; ++t)
        #pragma unroll
        for (int mt = 0; mt < 2; ++mt)
            #pragma unroll
            for (int nt = 0; nt < 4; ++nt)
                #pragma unroll
                for (int c = 0; c < 4; ++c)
                    tw[t][mt][nt][c] = 0.f;

    // --- main loop: 12 experts, B streamed straight from L2 via LDG.128.NC
    #pragma unroll 1
    for (int e = 0; e < N_EXPERTS; ++e) {
        float acc[2][4][4];
        #pragma unroll
        for (int mt = 0; mt < 2; ++mt)
            #pragma unroll
            for (int nt = 0; nt < 4; ++nt)
                #pragma unroll
                for (int c = 0; c < 4; ++c)
                    acc[mt][nt][c] = 0.f;

        const char* bp = bbase + (size_t)e * 65536;
        #pragma unroll 4
        for (int ks = 0; ks < 16; ++ks) {
            uint4 A0 = *(const uint4*)(ap + ks * 2048);
            uint4 A1 = *(const uint4*)(ap + ks * 2048 + 512);
            uint4 B0 = __ldg((const uint4*)(bp + ks * 4096));
            uint4 B1 = __ldg((const uint4*)(bp + ks * 4096 + 512));
            const uint32_t* ua0 = (const uint32_t*)&A0;
            const uint32_t* ua1 = (const uint32_t*)&A1;
            mma_f16(acc[0][0], ua0, B0.x, B0.y);
            mma_f16(acc[0][1], ua0, B0.z, B0.w);
            mma_f16(acc[0][2], ua0, B1.x, B1.y);
            mma_f16(acc[0][3], ua0, B1.z, B1.w);
            mma_f16(acc[1][0], ua1, B0.x, B0.y);
            mma_f16(acc[1][1], ua1, B0.z, B0.w);
            mma_f16(acc[1][2], ua1, B1.x, B1.y);
            mma_f16(acc[1][3], ua1, B1.z, B1.w);
        }

        // --- epilogue: bias + ReLU + gate-weighted accumulate (registers)
        #pragma unroll
        for (int mt = 0; mt < 2; ++mt) {
            int rA = m0 + mt * 16 + gid;
            int rB = rA + 8;
            if (e < N_SHARE) {
                float gA0 = gs[rA * 17 + e],     gB0 = gs[rB * 17 + e];
                float gA1 = gs[rA * 17 + 8 + e], gB1 = gs[rB * 17 + 8 + e];
                #pragma unroll
                for (int nt = 0; nt < 4; ++nt) {
                    int h = hb * 32 + nt * 8 + tig * 2;
                    float b0 = bs[e * H_DIM + h];
                    float b1 = bs[e * H_DIM + h + 1];
                    float v0 = fmaxf(acc[mt][nt][0] + b0, 0.f);
                    float v1 = fmaxf(acc[mt][nt][1] + b1, 0.f);
                    float v2 = fmaxf(acc[mt][nt][2] + b0, 0.f);
                    float v3 = fmaxf(acc[mt][nt][3] + b1, 0.f);
                    tw[0][mt][nt][0] += gA0 * v0;  tw[0][mt][nt][1] += gA0 * v1;
                    tw[0][mt][nt][2] += gB0 * v2;  tw[0][mt][nt][3] += gB0 * v3;
                    tw[1][mt][nt][0] += gA1 * v0;  tw[1][mt][nt][1] += gA1 * v1;
                    tw[1][mt][nt][2] += gB1 * v2;  tw[1][mt][nt][3] += gB1 * v3;
                }
            } else {
                int et = e - N_SHARE;
                int tt = et >> 2;
                int gcol = tt * 8 + 4 + (et & 3);
                float gA = gs[rA * 17 + gcol];
                float gB = gs[rB * 17 + gcol];
                float* twt = &tw[tt][mt][0][0];
                #pragma unroll
                for (int nt = 0; nt < 4; ++nt) {
                    int h = hb * 32 + nt * 8 + tig * 2;
                    float b0 = bs[e * H_DIM + h];
                    float b1 = bs[e * H_DIM + h + 1];
                    twt[nt * 4 + 0] += gA * fmaxf(acc[mt][nt][0] + b0, 0.f);
                    twt[nt * 4 + 1] += gA * fmaxf(acc[mt][nt][1] + b1, 0.f);
                    twt[nt * 4 + 2] += gB * fmaxf(acc[mt][nt][2] + b0, 0.f);
                    twt[nt * 4 + 3] += gB * fmaxf(acc[mt][nt][3] + b1, 0.f);
                }
            }
        }
    }

    // --- write towers [2][B][128]
    #pragma unroll
    for (int t = 0; t < 2; ++t) {
        #pragma unroll
        for (int mt = 0; mt < 2; ++mt) {
            size_t rA = (size_t)row0 + m0 + mt * 16 + gid;
            float* baseA = out + ((size_t)t * Btot + rA) * H_DIM;
            float* baseB = baseA + 8 * H_DIM;
            #pragma unroll
            for (int nt = 0; nt < 4; ++nt) {
                int h = hb * 32 + nt * 8 + tig * 2;
                *(float2*)(baseA + h) = make_float2(tw[t][mt][nt][0], tw[t][mt][nt][1]);
                *(float2*)(baseB + h) = make_float2(tw[t][mt][nt][2], tw[t][mt][nt][3]);
            }
        }
    }
}

extern "C" void kernel_launch(void* const* d_in, const int* in_sizes, int n_in,
                              void* d_out, int out_size) {
    const float* x   = (const float*)d_in[0];
    const float* Wsh = (const float*)d_in[1];
    const float* bsh = (const float*)d_in[2];
    const float* Wtk = (const float*)d_in[3];
    const float* btk = (const float*)d_in[4];
    const float* Wg  = (const float*)d_in[5];
    const float* bg  = (const float*)d_in[6];
    float* out = (float*)d_out;

    int Btot = in_sizes[0] / D_IN;                // 32768
    int nslots = N_EXPERTS * 4096 + 512;          // 49664
    dmoe_wprep<<<(nslots + 255) / 256, 256>>>(Wsh, Wtk, Wg);

    cudaFuncSetAttribute(dmoe_fused_kernel,
                         cudaFuncAttributeMaxDynamicSharedMemorySize, SMEM_BYTES);
    dmoe_fused_kernel<<<Btot / M_TILE, THREADS, SMEM_BYTES>>>(
        x, bsh, btk, bg, out, Btot);
}